// round 14
// baseline (speedup 1.0000x reference)
#include <cuda_runtime.h>
#include <cuda_bf16.h>

// HintGenKernelBatched: masked XOR-parity gather-reduce.
//   entries:        [1000000, 5]  int32
//   padded_indices: [4096, 2048]  int32 in [0, 1e6)
//   valid_mask:     [4096, 2048]  int32 in {0, 1}
//   out:            [4096, 5]     float32 (numeric convert; values < 2^31)
//
// Converged model (R6-R12): kernel is L2-byte-bound (~265MB LTS @ ~9.8TB/s in
// the warm timed loop); latency/instruction restructures are neutral. This
// round: (a) revert phase 1 to R10's exact best-measured compaction, and
// (b) PERSISTENT grid = 148 SMs x 8 CTAs = 1184 CTAs, each looping hints with
// stride 1184 -> removes the 3.46-wave quantization tail + wave transitions.

#define MAX_SUBSET 2048
#define ROW 5
#define THREADS 256
#define WARPS (THREADS / 32)
#define SLOTS_PER_WARP (MAX_SUBSET / WARPS)     // 256
#define SEG 264                                 // 256 max valid + sentinels
#define GRID_CTAS (148 * 8)                     // one full resident wave (B200)

__global__ __launch_bounds__(THREADS, 8) void hint_parity_kernel(
    const int* __restrict__ entries,
    const int* __restrict__ padded_indices,
    const int* __restrict__ valid_mask,
    float* __restrict__ out,
    int num_hints)
{
    __shared__ int scomp[WARPS][SEG];           // per-warp compacted indices
    __shared__ unsigned red[WARPS][ROW];

    const int t    = threadIdx.x;
    const int warp = t >> 5;
    const int lane = t & 31;
    const unsigned lmask = (1u << lane) - 1u;

    for (int h = blockIdx.x; h < num_hints; h += GRID_CTAS) {
        const size_t base = (size_t)h * MAX_SUBSET;
        const int4* __restrict__ idx4 =
            reinterpret_cast<const int4*>(padded_indices + base) + warp * (SLOTS_PER_WARP / 4);
        const int4* __restrict__ msk4 =
            reinterpret_cast<const int4*>(valid_mask + base) + warp * (SLOTS_PER_WARP / 4);

        // ---- Phase 1: stream + warp-local compaction (R10 verbatim) ----
        unsigned cnt = 0;

        #pragma unroll
        for (int i = 0; i < SLOTS_PER_WARP / (32 * 4); ++i) {   // 2 iterations
            const int4 iv = idx4[i * 32 + lane];                // LDG.128 coalesced
            const int4 mv = msk4[i * 32 + lane];

            #define COMPACT(IC, MC)                                             \
                {                                                               \
                    const unsigned bal = __ballot_sync(0xffffffffu, (MC) != 0); \
                    if (MC) scomp[warp][cnt + __popc(bal & lmask)] = (IC);      \
                    cnt += __popc(bal);                                         \
                }
            COMPACT(iv.x, mv.x)
            COMPACT(iv.y, mv.y)
            COMPACT(iv.z, mv.z)
            COMPACT(iv.w, mv.w)
            #undef COMPACT
        }
        // sentinel pad so the dense loop rounds up to a multiple of 4
        if (lane < 4) scomp[warp][cnt + lane] = -1;
        __syncwarp();

        // ---- Phase 2: dense cooperative gather (R10 geometry) ----
        // 4 groups of 8 lanes; group g takes compacted slot it*4+g; lane j<5
        // loads word j of that row. Every LDG covers 4 valid rows.
        const int j  = lane & 7;
        const int g  = lane >> 3;
        const bool wl = (j < ROW);

        unsigned acc = 0;
        const int nit = (int)((cnt + 3) >> 2);

        #pragma unroll 4
        for (int it = 0; it < nit; ++it) {
            const int q = scomp[warp][it * 4 + g];  // LDS.32, group-broadcast
            if (wl && q >= 0) {
                acc ^= (unsigned)__ldg(entries + (size_t)(unsigned)q * ROW + j);
            }
        }

        // ---- Reduce the 4 groups of each warp ----
        acc ^= __shfl_xor_sync(0xffffffffu, acc, 8);
        acc ^= __shfl_xor_sync(0xffffffffu, acc, 16);

        if (lane < ROW) red[warp][lane] = acc;
        __syncthreads();

        // ---- Fold 8 warps, store float32 ----
        if (t < ROW) {
            unsigned v = red[0][t];
            #pragma unroll
            for (int w = 1; w < WARPS; ++w) v ^= red[w][t];
            out[(size_t)h * ROW + t] = (float)v;    // numeric convert, < 2^31
        }
        __syncthreads();    // protect scomp/red reuse for the next hint
    }
}

extern "C" void kernel_launch(void* const* d_in, const int* in_sizes, int n_in,
                              void* d_out, int out_size)
{
    const int* entries        = (const int*)d_in[0];
    const int* padded_indices = (const int*)d_in[1];
    const int* valid_mask     = (const int*)d_in[2];
    float* out = (float*)d_out;

    const int num_hints = out_size / ROW;  // 4096
    const int grid = (num_hints < GRID_CTAS) ? num_hints : GRID_CTAS;
    hint_parity_kernel<<<grid, THREADS>>>(entries, padded_indices, valid_mask, out, num_hints);
}

// round 16
// speedup vs baseline: 1.0201x; 1.0201x over previous
#include <cuda_runtime.h>
#include <cuda_bf16.h>

// HintGenKernelBatched: masked XOR-parity gather-reduce.
//   entries:        [1000000, 5]  int32
//   padded_indices: [4096, 2048]  int32 in [0, 1e6)
//   valid_mask:     [4096, 2048]  int32 in {0, 1}
//   out:            [4096, 5]     float32 (numeric convert; values < 2^31)
//
// R14 post-mortem: persistent grid RETIRED (intra-CTA hint serialization cost
// > wave-tail savings; independent CTAs overlap naturally). This is R10 --
// the measured-best variant (27.0us) -- verbatim, with one delta: gather
// loop unroll 4 -> 8 (deeper LDG batching per scheduling window).
//
// Converged model: L2-byte + L1-wavefront bound (~265MB LTS warm, ~4.9M
// gather wavefronts). Wins came only from deleting wavefronts/dead slots.

#define MAX_SUBSET 2048
#define ROW 5
#define THREADS 256
#define WARPS (THREADS / 32)
#define SLOTS_PER_WARP (MAX_SUBSET / WARPS)     // 256
#define SEG 296                                 // 256 max valid + 32 sentinel pad

__global__ __launch_bounds__(THREADS, 8) void hint_parity_kernel(
    const int* __restrict__ entries,
    const int* __restrict__ padded_indices,
    const int* __restrict__ valid_mask,
    float* __restrict__ out)
{
    __shared__ int scomp[WARPS][SEG];           // per-warp compacted indices
    __shared__ unsigned red[WARPS][ROW];

    const int h    = blockIdx.x;
    const int t    = threadIdx.x;
    const int warp = t >> 5;
    const int lane = t & 31;
    const size_t base = (size_t)h * MAX_SUBSET;

    const int4* __restrict__ idx4 =
        reinterpret_cast<const int4*>(padded_indices + base) + warp * (SLOTS_PER_WARP / 4);
    const int4* __restrict__ msk4 =
        reinterpret_cast<const int4*>(valid_mask + base) + warp * (SLOTS_PER_WARP / 4);

    // ---- Phase 1: stream + warp-local compaction (R10 verbatim) ----
    unsigned cnt = 0;
    const unsigned lmask = (1u << lane) - 1u;

    #pragma unroll
    for (int i = 0; i < SLOTS_PER_WARP / (32 * 4); ++i) {   // 2 iterations
        const int4 iv = idx4[i * 32 + lane];                // LDG.128 coalesced
        const int4 mv = msk4[i * 32 + lane];

        #define COMPACT(IC, MC)                                             \
            {                                                               \
                const unsigned bal = __ballot_sync(0xffffffffu, (MC) != 0); \
                if (MC) scomp[warp][cnt + __popc(bal & lmask)] = (IC);      \
                cnt += __popc(bal);                                         \
            }
        COMPACT(iv.x, mv.x)
        COMPACT(iv.y, mv.y)
        COMPACT(iv.z, mv.z)
        COMPACT(iv.w, mv.w)
        #undef COMPACT
    }
    // sentinel pad so the dense loop rounds up to a multiple of 8*4 rows
    scomp[warp][cnt + lane] = -1;
    __syncwarp();

    // ---- Phase 2: dense cooperative gather (R10 geometry, unroll 8) ----
    // 4 groups of 8 lanes; group g takes compacted slot it*4+g; lane j<5
    // loads word j of that row. Every LDG covers 4 valid rows.
    const int j  = lane & 7;
    const int g  = lane >> 3;
    const bool wl = (j < ROW);

    unsigned acc = 0;
    const int nit = (int)((cnt + 3) >> 2);

    #pragma unroll 8
    for (int it = 0; it < nit; ++it) {
        const int q = scomp[warp][it * 4 + g];  // LDS.32, group-broadcast
        if (wl && q >= 0) {
            acc ^= (unsigned)__ldg(entries + (size_t)(unsigned)q * ROW + j);
        }
    }

    // ---- Reduce the 4 groups of each warp ----
    acc ^= __shfl_xor_sync(0xffffffffu, acc, 8);
    acc ^= __shfl_xor_sync(0xffffffffu, acc, 16);

    // lanes 0..4 hold the warp's parity for words 0..4
    if (lane < ROW) red[warp][lane] = acc;
    __syncthreads();

    // ---- Fold 8 warps, store float32 ----
    if (t < ROW) {
        unsigned v = red[0][t];
        #pragma unroll
        for (int w = 1; w < WARPS; ++w) v ^= red[w][t];
        out[(size_t)h * ROW + t] = (float)v;    // numeric convert, values < 2^31
    }
}

extern "C" void kernel_launch(void* const* d_in, const int* in_sizes, int n_in,
                              void* d_out, int out_size)
{
    const int* entries        = (const int*)d_in[0];
    const int* padded_indices = (const int*)d_in[1];
    const int* valid_mask     = (const int*)d_in[2];
    float* out = (float*)d_out;

    const int num_hints = out_size / ROW;  // 4096
    hint_parity_kernel<<<num_hints, THREADS>>>(entries, padded_indices, valid_mask, out);
}